// round 4
// baseline (speedup 1.0000x reference)
#include <cuda_runtime.h>
#include <cuda_bf16.h>
#include <stdint.h>
#include <math.h>

#define SEQ 2048
#define HDIM 1024
#define NLAYER 4
#define NH 16
#define NKV 4
#define HD 64
#define IDIM 4096
#define VOCAB 32000

// ---------------- scratch (static device globals; no allocations) ----------------
__device__ float g_h[SEQ * HDIM];
__device__ float g_norm[SEQ * HDIM];
__device__ float g_q[SEQ * NH * HD];
__device__ float g_kraw[SEQ * NKV * HD];
__device__ float g_kT[NKV * HD * SEQ];   // [kvh][d][s]
__device__ float g_v[SEQ * NKV * HD];
__device__ float g_att[SEQ * NH * HD];
__device__ float g_gate[SEQ * IDIM];
__device__ float g_up[SEQ * IDIM];

// ---------------- tf32 helpers ----------------
__device__ __forceinline__ uint32_t cvt_tf32(float x) {
    uint32_t r;
    asm("cvt.rna.tf32.f32 %0, %1;" : "=r"(r) : "f"(x));
    return r;
}

__device__ __forceinline__ void mma_tf32(float* c, const uint32_t* a, const uint32_t* b) {
    asm volatile(
        "mma.sync.aligned.m16n8k8.row.col.f32.tf32.tf32.f32 "
        "{%0,%1,%2,%3}, {%4,%5,%6,%7}, {%8,%9}, {%0,%1,%2,%3};"
        : "+f"(c[0]), "+f"(c[1]), "+f"(c[2]), "+f"(c[3])
        : "r"(a[0]), "r"(a[1]), "r"(a[2]), "r"(a[3]), "r"(b[0]), "r"(b[1]));
}

// ---------------- embedding + audio scatter ----------------
__global__ void embed_scatter_kernel(const int* __restrict__ ids,
                                     const float* __restrict__ emb,
                                     const float* __restrict__ audio,
                                     const int* __restrict__ aoff,
                                     float* __restrict__ h) {
    int s = blockIdx.x;
    int off = aoff[0];
    const float* src;
    if (s >= off && s < off + 256) src = audio + (size_t)(s - off) * HDIM;
    else                           src = emb + (size_t)ids[s] * HDIM;
    float* dst = h + (size_t)s * HDIM;
    int i = threadIdx.x * 4;
    *(float4*)&dst[i] = *(const float4*)&src[i];
}

// ---------------- RMSNorm over H=1024 ----------------
__global__ void rmsnorm_kernel(const float* __restrict__ x,
                               const float* __restrict__ w,
                               float* __restrict__ out) {
    int s = blockIdx.x;
    const float* xr = x + (size_t)s * HDIM;
    float ss = 0.f;
#pragma unroll
    for (int i = 0; i < 4; i++) { float v = xr[threadIdx.x + i * 256]; ss += v * v; }
    __shared__ float red[8];
#pragma unroll
    for (int o = 16; o; o >>= 1) ss += __shfl_xor_sync(0xffffffffu, ss, o);
    if ((threadIdx.x & 31) == 0) red[threadIdx.x >> 5] = ss;
    __syncthreads();
    if (threadIdx.x < 32) {
        float v = (threadIdx.x < 8) ? red[threadIdx.x] : 0.f;
#pragma unroll
        for (int o = 4; o; o >>= 1) v += __shfl_xor_sync(0xffffffffu, v, o);
        if (threadIdx.x == 0) red[0] = v;
    }
    __syncthreads();
    float r = rsqrtf(red[0] * (1.f / HDIM) + 1e-6f);
    float* orow = out + (size_t)s * HDIM;
#pragma unroll
    for (int i = 0; i < 4; i++) { int id = threadIdx.x + i * 256; orow[id] = xr[id] * r * w[id]; }
}

// ---------------- per-head RMSNorm (HD=64) + RoPE ----------------
__global__ void rms_rope_kernel(const float* __restrict__ in,
                                const float* __restrict__ w,
                                const int* __restrict__ pos_ids,
                                float* __restrict__ out_nat,
                                float* __restrict__ out_T,
                                float* __restrict__ present,
                                int nh) {
    int s = blockIdx.x;
    int warp = threadIdx.x >> 5, lane = threadIdx.x & 31;
    int h = blockIdx.y * 4 + warp;
    if (h >= nh) return;
    const float* x = in + (size_t)s * nh * HD + h * HD;
    float x0 = x[lane], x1 = x[lane + 32];
    float ss = x0 * x0 + x1 * x1;
#pragma unroll
    for (int o = 16; o; o >>= 1) ss += __shfl_xor_sync(0xffffffffu, ss, o);
    float r = rsqrtf(ss * (1.f / HD) + 1e-6f);
    x0 = x0 * r * w[lane];
    x1 = x1 * r * w[lane + 32];
    float pos = (float)pos_ids[s];
    float invf = expf(-((float)lane * (1.f / 32.f)) * 9.210340371976184f);
    float ang = pos * invf;
    float c, sn;
    sincosf(ang, &sn, &c);
    float o0 = x0 * c - x1 * sn;
    float o1 = x1 * c + x0 * sn;
    if (out_nat) {
        float* op = out_nat + (size_t)s * nh * HD + h * HD;
        op[lane] = o0; op[lane + 32] = o1;
    }
    if (out_T) {
        out_T[(size_t)(h * HD + lane) * SEQ + s] = o0;
        out_T[(size_t)(h * HD + lane + 32) * SEQ + s] = o1;
    }
    if (present) {
        float* pp = present + ((size_t)h * SEQ + s) * HD;
        pp[lane] = o0; pp[lane + 32] = o1;
    }
}

// ---------------- copy V into present_values [NKV,S,HD] ----------------
__global__ void copy_v_kernel(const float* __restrict__ v, float* __restrict__ pv) {
    int s = blockIdx.x;
    int t = threadIdx.x;
    int kv = t >> 6, d = t & 63;
    pv[((size_t)kv * SEQ + s) * HD + d] = v[(size_t)s * (NKV * HD) + t];
}

// ---------------- 3xTF32 tensor-core GEMM (fp32 accuracy) ----------------
// C[M,N] = (Res?) + A[M,K] @ B[K,N], row-major, M%128==0, N%128==0, K%32==0.
// 128x128x32 tiles, 8 warps (2x4), 64x32 warp tiles of m16n8k8 mma.
// Smem holds raw fp32 in fragment-permuted order; hi/lo tf32 split happens in
// registers; 3 mmas per fragment pair: ah*bh + ah*bl + al*bh.
__global__ __launch_bounds__(256) void gemm_tf32_kernel(const float* __restrict__ A,
                                                        const float* __restrict__ B,
                                                        const float* __restrict__ Res,
                                                        float* __restrict__ C,
                                                        int M, int N, int K) {
    // As[ik][im][lane][reg] : 4*8*32*4 ; Bs[ik][in][lane][reg] : 4*16*32*2
    __shared__ uint32_t As[4096];
    __shared__ uint32_t Bs[4096];

    int tid = threadIdx.x;
    int lane = tid & 31, warp = tid >> 5;
    int wm = warp >> 2, wn = warp & 3;
    int bm = blockIdx.y * 128, bn = blockIdx.x * 128;

    float acc[4][4][4];
#pragma unroll
    for (int im = 0; im < 4; im++)
#pragma unroll
        for (int in = 0; in < 4; in++)
#pragma unroll
            for (int r = 0; r < 4; r++) acc[im][in][r] = 0.f;

    float4 pa[4], pb[4];

    // ---- load tile at k0base into registers ----
#define LDG_TILE(k0base)                                                            \
    {                                                                               \
        _Pragma("unroll")                                                           \
        for (int i = 0; i < 4; i++) {                                               \
            int f = tid + i * 256;                                                  \
            pa[i] = *(const float4*)(A + (size_t)(bm + (f >> 3)) * K + (k0base) + ((f & 7) << 2)); \
            pb[i] = *(const float4*)(B + (size_t)((k0base) + (f >> 5)) * N + bn + ((f & 31) << 2)); \
        }                                                                           \
    }

    // ---- scatter raw fp32 bits into fragment-permuted smem ----
#define STS_TILE()                                                                  \
    {                                                                               \
        _Pragma("unroll")                                                           \
        for (int i = 0; i < 4; i++) {                                               \
            {                                                                       \
                int f = tid + i * 256;                                              \
                int r = f >> 3, k0 = (f & 7) << 2;                                  \
                int im = r >> 4, rr = r & 15;                                       \
                int ik = k0 >> 3, reg = (rr >> 3) + (((k0 >> 2) & 1) << 1);         \
                int base = ((ik * 8 + im) * 32 + ((rr & 7) << 2)) * 4 + reg;        \
                const float* v = (const float*)&pa[i];                              \
                _Pragma("unroll")                                                   \
                for (int e = 0; e < 4; e++) As[base + e * 4] = __float_as_uint(v[e]); \
            }                                                                       \
            {                                                                       \
                int f = tid + i * 256;                                              \
                int k = f >> 5, n0 = (f & 31) << 2;                                 \
                int ik = k >> 3, kk = k & 7;                                        \
                int reg = kk >> 2;                                                  \
                const float* v = (const float*)&pb[i];                              \
                _Pragma("unroll")                                                   \
                for (int e = 0; e < 4; e++) {                                       \
                    int n = n0 + e;                                                 \
                    Bs[((ik * 16 + (n >> 3)) * 32 + (n & 7) * 4 + (kk & 3)) * 2 + reg] = __float_as_uint(v[e]); \
                }                                                                   \
            }                                                                       \
        }                                                                           \
    }

    // ---- compute 32 k-steps from smem with 3xTF32 split ----
#define COMPUTE()                                                                   \
    {                                                                               \
        _Pragma("unroll")                                                           \
        for (int ik = 0; ik < 4; ik++) {                                            \
            uint32_t ah[4][4], al[4][4], bh[4][2], bl[4][2];                        \
            _Pragma("unroll")                                                       \
            for (int im = 0; im < 4; im++) {                                        \
                uint32_t raw[4];                                                    \
                *(uint4*)raw = *(const uint4*)&As[((ik * 8 + wm * 4 + im) * 32 + lane) * 4]; \
                _Pragma("unroll")                                                   \
                for (int r = 0; r < 4; r++) {                                       \
                    float x = __uint_as_float(raw[r]);                              \
                    uint32_t h_ = cvt_tf32(x);                                      \
                    ah[im][r] = h_;                                                 \
                    al[im][r] = cvt_tf32(x - __uint_as_float(h_));                  \
                }                                                                   \
            }                                                                       \
            _Pragma("unroll")                                                       \
            for (int in = 0; in < 4; in++) {                                        \
                uint32_t raw[2];                                                    \
                *(uint2*)raw = *(const uint2*)&Bs[((ik * 16 + wn * 4 + in) * 32 + lane) * 2]; \
                _Pragma("unroll")                                                   \
                for (int r = 0; r < 2; r++) {                                       \
                    float x = __uint_as_float(raw[r]);                              \
                    uint32_t h_ = cvt_tf32(x);                                      \
                    bh[in][r] = h_;                                                 \
                    bl[in][r] = cvt_tf32(x - __uint_as_float(h_));                  \
                }                                                                   \
            }                                                                       \
            _Pragma("unroll")                                                       \
            for (int im = 0; im < 4; im++)                                          \
                _Pragma("unroll")                                                   \
                for (int in = 0; in < 4; in++) {                                    \
                    mma_tf32(acc[im][in], ah[im], bl[in]);                          \
                    mma_tf32(acc[im][in], al[im], bh[in]);                          \
                    mma_tf32(acc[im][in], ah[im], bh[in]);                          \
                }                                                                   \
        }                                                                           \
    }

    LDG_TILE(0);
    STS_TILE();
    __syncthreads();

    for (int k0 = 32; k0 < K; k0 += 32) {
        LDG_TILE(k0);
        COMPUTE();
        __syncthreads();
        STS_TILE();
        __syncthreads();
    }
    COMPUTE();

    // ---- epilogue ----
    int gid = lane >> 2, tig = lane & 3;
#pragma unroll
    for (int im = 0; im < 4; im++) {
#pragma unroll
        for (int in = 0; in < 4; in++) {
            int row0 = bm + wm * 64 + im * 16 + gid;
            int col = bn + wn * 32 + in * 8 + tig * 2;
            float2 v0 = make_float2(acc[im][in][0], acc[im][in][1]);
            float2 v1 = make_float2(acc[im][in][2], acc[im][in][3]);
            if (Res) {
                float2 r0 = *(const float2*)(Res + (size_t)row0 * N + col);
                float2 r1 = *(const float2*)(Res + (size_t)(row0 + 8) * N + col);
                v0.x += r0.x; v0.y += r0.y;
                v1.x += r1.x; v1.y += r1.y;
            }
            *(float2*)(C + (size_t)row0 * N + col) = v0;
            *(float2*)(C + (size_t)(row0 + 8) * N + col) = v1;
        }
    }
#undef LDG_TILE
#undef STS_TILE
#undef COMPUTE
}

// ---------------- flash attention: 64q x 64k tiles, online softmax ----------------
__global__ __launch_bounds__(256) void attn_kernel(const float* __restrict__ q,
                                                   const float* __restrict__ kT,
                                                   const float* __restrict__ v,
                                                   float* __restrict__ o) {
    extern __shared__ float sm[];
    float* Qs  = sm;
    float* Kst = sm + 4096;
    float* Vs  = sm + 8192;
    float* Ps  = sm + 12288;
    int qt = blockIdx.x, h = blockIdx.y, kvh = h >> 2;
    int tid = threadIdx.x;
    int tr = tid >> 4, tc = tid & 15;

#pragma unroll
    for (int it = 0; it < 4; it++) {
        int idx = tid + it * 256;
        int rr = idx >> 4, dv = (idx & 15) << 2;
        *(float4*)&Qs[rr * 64 + dv] =
            *(const float4*)&q[(size_t)(qt * 64 + rr) * (NH * HD) + h * HD + dv];
    }

    float m[4], l[4], acc[4][4];
#pragma unroll
    for (int i = 0; i < 4; i++) {
        m[i] = -1e30f; l[i] = 0.f;
#pragma unroll
        for (int j = 0; j < 4; j++) acc[i][j] = 0.f;
    }

    for (int kt = 0; kt <= qt; kt++) {
        __syncthreads();
#pragma unroll
        for (int it = 0; it < 4; it++) {
            int idx = tid + it * 256;
            int a = idx >> 4, bv = (idx & 15) << 2;
            *(float4*)&Kst[a * 64 + bv] =
                *(const float4*)&kT[(size_t)(kvh * HD + a) * SEQ + kt * 64 + bv];
            *(float4*)&Vs[a * 64 + bv] =
                *(const float4*)&v[(size_t)(kt * 64 + a) * (NKV * HD) + kvh * HD + bv];
        }
        __syncthreads();

        float sc[4][4];
#pragma unroll
        for (int i = 0; i < 4; i++)
#pragma unroll
            for (int j = 0; j < 4; j++) sc[i][j] = 0.f;

#pragma unroll 8
        for (int d = 0; d < 64; d++) {
            float4 b = *(float4*)&Kst[d * 64 + tc * 4];
            float a0 = Qs[(tr * 4 + 0) * 64 + d];
            float a1 = Qs[(tr * 4 + 1) * 64 + d];
            float a2 = Qs[(tr * 4 + 2) * 64 + d];
            float a3 = Qs[(tr * 4 + 3) * 64 + d];
            sc[0][0] += a0 * b.x; sc[0][1] += a0 * b.y; sc[0][2] += a0 * b.z; sc[0][3] += a0 * b.w;
            sc[1][0] += a1 * b.x; sc[1][1] += a1 * b.y; sc[1][2] += a1 * b.z; sc[1][3] += a1 * b.w;
            sc[2][0] += a2 * b.x; sc[2][1] += a2 * b.y; sc[2][2] += a2 * b.z; sc[2][3] += a2 * b.w;
            sc[3][0] += a3 * b.x; sc[3][1] += a3 * b.y; sc[3][2] += a3 * b.z; sc[3][3] += a3 * b.w;
        }

        bool diag = (kt == qt);
#pragma unroll
        for (int i = 0; i < 4; i++) {
            int qrow = qt * 64 + tr * 4 + i;
            float tm_ = -1e30f;
#pragma unroll
            for (int j = 0; j < 4; j++) {
                float val = sc[i][j] * 0.125f;
                if (diag && (kt * 64 + tc * 4 + j) > qrow) val = -1e30f;
                sc[i][j] = val;
                tm_ = fmaxf(tm_, val);
            }
            tm_ = fmaxf(tm_, __shfl_xor_sync(0xffffffffu, tm_, 1));
            tm_ = fmaxf(tm_, __shfl_xor_sync(0xffffffffu, tm_, 2));
            tm_ = fmaxf(tm_, __shfl_xor_sync(0xffffffffu, tm_, 4));
            tm_ = fmaxf(tm_, __shfl_xor_sync(0xffffffffu, tm_, 8));
            float mn = fmaxf(m[i], tm_);
            float scal = expf(m[i] - mn);
            float ps = 0.f;
#pragma unroll
            for (int j = 0; j < 4; j++) {
                float p = expf(sc[i][j] - mn);
                sc[i][j] = p;
                ps += p;
            }
            ps += __shfl_xor_sync(0xffffffffu, ps, 1);
            ps += __shfl_xor_sync(0xffffffffu, ps, 2);
            ps += __shfl_xor_sync(0xffffffffu, ps, 4);
            ps += __shfl_xor_sync(0xffffffffu, ps, 8);
            l[i] = l[i] * scal + ps;
            m[i] = mn;
#pragma unroll
            for (int j = 0; j < 4; j++) {
                acc[i][j] *= scal;
                Ps[(tr * 4 + i) * 64 + tc * 4 + j] = sc[i][j];
            }
        }
        __syncwarp();

#pragma unroll 8
        for (int j = 0; j < 64; j++) {
            float4 b = *(float4*)&Vs[j * 64 + tc * 4];
            float p0 = Ps[(tr * 4 + 0) * 64 + j];
            float p1 = Ps[(tr * 4 + 1) * 64 + j];
            float p2 = Ps[(tr * 4 + 2) * 64 + j];
            float p3 = Ps[(tr * 4 + 3) * 64 + j];
            acc[0][0] += p0 * b.x; acc[0][1] += p0 * b.y; acc[0][2] += p0 * b.z; acc[0][3] += p0 * b.w;
            acc[1][0] += p1 * b.x; acc[1][1] += p1 * b.y; acc[1][2] += p1 * b.z; acc[1][3] += p1 * b.w;
            acc[2][0] += p2 * b.x; acc[2][1] += p2 * b.y; acc[2][2] += p2 * b.z; acc[2][3] += p2 * b.w;
            acc[3][0] += p3 * b.x; acc[3][1] += p3 * b.y; acc[3][2] += p3 * b.z; acc[3][3] += p3 * b.w;
        }
    }

#pragma unroll
    for (int i = 0; i < 4; i++) {
        float inv = 1.f / l[i];
        int row = qt * 64 + tr * 4 + i;
        float4 ov;
        ov.x = acc[i][0] * inv; ov.y = acc[i][1] * inv;
        ov.z = acc[i][2] * inv; ov.w = acc[i][3] * inv;
        *(float4*)&o[(size_t)row * (NH * HD) + h * HD + tc * 4] = ov;
    }
}

// ---------------- silu(g) * u ----------------
__global__ void silu_mul_kernel(const float* __restrict__ g, const float* __restrict__ u,
                                float* __restrict__ out, int n) {
    int i = blockIdx.x * 256 + threadIdx.x;
    if (i < n) {
        float x = g[i];
        float sg = 1.f / (1.f + expf(-x));
        out[i] = x * sg * u[i];
    }
}

// ---------------- host launch ----------------
extern "C" void kernel_launch(void* const* d_in, const int* in_sizes, int n_in,
                              void* d_out, int out_size) {
    (void)in_sizes; (void)n_in; (void)out_size;

    static bool init = false;
    static float *p_h, *p_norm, *p_q, *p_kraw, *p_kT, *p_v, *p_att, *p_gate, *p_up;
    if (!init) {
        cudaGetSymbolAddress((void**)&p_h, g_h);
        cudaGetSymbolAddress((void**)&p_norm, g_norm);
        cudaGetSymbolAddress((void**)&p_q, g_q);
        cudaGetSymbolAddress((void**)&p_kraw, g_kraw);
        cudaGetSymbolAddress((void**)&p_kT, g_kT);
        cudaGetSymbolAddress((void**)&p_v, g_v);
        cudaGetSymbolAddress((void**)&p_att, g_att);
        cudaGetSymbolAddress((void**)&p_gate, g_gate);
        cudaGetSymbolAddress((void**)&p_up, g_up);
        cudaFuncSetAttribute(attn_kernel, cudaFuncAttributeMaxDynamicSharedMemorySize, 65536);
        init = true;
    }

    const int*   ids    = (const int*)d_in[0];
    const int*   pos    = (const int*)d_in[1];
    const float* audio  = (const float*)d_in[2];
    const int*   aoff   = (const int*)d_in[3];
    const float* embw   = (const float*)d_in[4];
    const float* q_w    = (const float*)d_in[5];
    const float* k_w    = (const float*)d_in[6];
    const float* v_w    = (const float*)d_in[7];
    const float* o_w    = (const float*)d_in[8];
    const float* qn_w   = (const float*)d_in[9];
    const float* kn_w   = (const float*)d_in[10];
    const float* ln1_w  = (const float*)d_in[11];
    const float* ln2_w  = (const float*)d_in[12];
    const float* gate_w = (const float*)d_in[13];
    const float* up_w   = (const float*)d_in[14];
    const float* down_w = (const float*)d_in[15];
    const float* norm_w = (const float*)d_in[16];
    const float* lm_w   = (const float*)d_in[17];

    float* out    = (float*)d_out;
    float* logits = out;
    float* pk     = out + (size_t)SEQ * VOCAB;
    float* pv     = pk + (size_t)NLAYER * NKV * SEQ * HD;

    embed_scatter_kernel<<<SEQ, 256>>>(ids, embw, audio, aoff, p_h);

    for (int l = 0; l < NLAYER; l++) {
        rmsnorm_kernel<<<SEQ, 256>>>(p_h, ln1_w + (size_t)l * HDIM, p_norm);

        gemm_tf32_kernel<<<dim3(NH * HD / 128, SEQ / 128), 256>>>(
            p_norm, q_w + (size_t)l * HDIM * NH * HD, nullptr, p_q, SEQ, NH * HD, HDIM);
        gemm_tf32_kernel<<<dim3(NKV * HD / 128, SEQ / 128), 256>>>(
            p_norm, k_w + (size_t)l * HDIM * NKV * HD, nullptr, p_kraw, SEQ, NKV * HD, HDIM);
        gemm_tf32_kernel<<<dim3(NKV * HD / 128, SEQ / 128), 256>>>(
            p_norm, v_w + (size_t)l * HDIM * NKV * HD, nullptr, p_v, SEQ, NKV * HD, HDIM);

        rms_rope_kernel<<<dim3(SEQ, 4), 128>>>(p_q, qn_w + (size_t)l * HD, pos,
                                               p_q, nullptr, nullptr, NH);
        rms_rope_kernel<<<dim3(SEQ, 1), 128>>>(p_kraw, kn_w + (size_t)l * HD, pos,
                                               nullptr, p_kT,
                                               pk + (size_t)l * NKV * SEQ * HD, NKV);
        copy_v_kernel<<<SEQ, 256>>>(p_v, pv + (size_t)l * NKV * SEQ * HD);

        attn_kernel<<<dim3(SEQ / 64, NH), 256, 65536>>>(p_q, p_kT, p_v, p_att);

        gemm_tf32_kernel<<<dim3(HDIM / 128, SEQ / 128), 256>>>(
            p_att, o_w + (size_t)l * NH * HD * HDIM, p_h, p_h, SEQ, HDIM, NH * HD);

        rmsnorm_kernel<<<SEQ, 256>>>(p_h, ln2_w + (size_t)l * HDIM, p_norm);

        gemm_tf32_kernel<<<dim3(IDIM / 128, SEQ / 128), 256>>>(
            p_norm, gate_w + (size_t)l * HDIM * IDIM, nullptr, p_gate, SEQ, IDIM, HDIM);
        gemm_tf32_kernel<<<dim3(IDIM / 128, SEQ / 128), 256>>>(
            p_norm, up_w + (size_t)l * HDIM * IDIM, nullptr, p_up, SEQ, IDIM, HDIM);

        silu_mul_kernel<<<(SEQ * IDIM) / 256, 256>>>(p_gate, p_up, p_gate, SEQ * IDIM);

        gemm_tf32_kernel<<<dim3(HDIM / 128, SEQ / 128), 256>>>(
            p_gate, down_w + (size_t)l * IDIM * HDIM, p_h, p_h, SEQ, HDIM, IDIM);
    }

    rmsnorm_kernel<<<SEQ, 256>>>(p_h, norm_w, p_norm);
    gemm_tf32_kernel<<<dim3(VOCAB / 128, SEQ / 128), 256>>>(
        p_norm, lm_w, nullptr, logits, SEQ, VOCAB, HDIM);
}

// round 6
// speedup vs baseline: 3.1704x; 3.1704x over previous
#include <cuda_runtime.h>
#include <cuda_bf16.h>
#include <stdint.h>
#include <math.h>

#define SEQ 2048
#define HDIM 1024
#define NLAYER 4
#define NH 16
#define NKV 4
#define HD 64
#define IDIM 4096
#define VOCAB 32000
#define QKVN 1536   // 16*64 + 4*64 + 4*64
#define GUN 8192    // 2*IDIM

// ---------------- scratch (static device globals; no allocations) ----------------
__device__ float g_h[SEQ * HDIM];
__device__ float g_norm[SEQ * HDIM];
__device__ float g_qkv[SEQ * QKVN];
__device__ float g_kT[NKV * HD * SEQ];   // [kvh][d][s]
__device__ float g_att[SEQ * NH * HD];
__device__ float g_gu[SEQ * GUN];
__device__ float g_act[SEQ * IDIM];

// prepped weights: fragment-ordered bf16 hi/lo pairs, 1 uint32 per element
__device__ uint32_t wp_qkv[NLAYER * HDIM * QKVN];
__device__ uint32_t wp_o[NLAYER * HDIM * HDIM];
__device__ uint32_t wp_gu[NLAYER * HDIM * GUN];
__device__ uint32_t wp_down[NLAYER * IDIM * HDIM];
__device__ uint32_t wp_lm[HDIM * VOCAB];

// ---------------- helpers ----------------
__device__ __forceinline__ uint32_t pack_bf16(float a, float b) {
    __nv_bfloat162 t = __floats2bfloat162_rn(a, b);  // .x = a (low 16), .y = b
    return *(uint32_t*)&t;
}

__device__ __forceinline__ void mma_bf16(float* c, const uint32_t* a, const uint32_t* b) {
    asm volatile(
        "mma.sync.aligned.m16n8k16.row.col.f32.bf16.bf16.f32 "
        "{%0,%1,%2,%3}, {%4,%5,%6,%7}, {%8,%9}, {%0,%1,%2,%3};"
        : "+f"(c[0]), "+f"(c[1]), "+f"(c[2]), "+f"(c[3])
        : "r"(a[0]), "r"(a[1]), "r"(a[2]), "r"(a[3]), "r"(b[0]), "r"(b[1]));
}

__device__ __forceinline__ void cp_async16(void* smem, const void* gmem) {
    uint32_t s = (uint32_t)__cvta_generic_to_shared(smem);
    asm volatile("cp.async.cg.shared.global [%0], [%1], 16;" :: "r"(s), "l"(gmem));
}
#define CP_COMMIT() asm volatile("cp.async.commit_group;")
#define CP_WAIT0()  asm volatile("cp.async.wait_group 0;")

// ---------------- weight prep: [K][N] f32 -> fragment-ordered bf16 hi/lo ----------------
// out tile (kt,nt): 1024 slots; slot = (ik*16+in)*32+lane; per slot uint4
// {hi(k=2c,2c+1), hi(k=2c+8,2c+9), lo(..), lo(..)} with n = nt*128+in*8+lane/4,
// k base = kt*32 + ik*16, c = lane%4. Source is up to 3 concatenated matrices over N.
__global__ void prep_w_kernel(const float* __restrict__ s0, int st0,
                              const float* __restrict__ s1, int st1,
                              const float* __restrict__ s2, int st2,
                              int n1, int n2, uint32_t* __restrict__ out) {
    int kt = blockIdx.y, nt = blockIdx.x, NT = gridDim.x;
    int t = threadIdx.x;
#pragma unroll
    for (int it = 0; it < 4; it++) {
        int slot = it * 256 + t;
        int lane = slot & 31, in = (slot >> 5) & 15, ik = slot >> 9;
        int g = lane >> 2, c = lane & 3;
        int n = nt * 128 + in * 8 + g;
        int kb = kt * 32 + ik * 16 + 2 * c;
        const float* src; int nn; int st;
        if (n >= n2)      { src = s2; nn = n - n2; st = st2; }
        else if (n >= n1) { src = s1; nn = n - n1; st = st1; }
        else              { src = s0; nn = n;      st = st0; }
        float x0 = src[(size_t)(kb + 0) * st + nn];
        float x1 = src[(size_t)(kb + 1) * st + nn];
        float x8 = src[(size_t)(kb + 8) * st + nn];
        float x9 = src[(size_t)(kb + 9) * st + nn];
        __nv_bfloat16 h0 = __float2bfloat16_rn(x0), h1 = __float2bfloat16_rn(x1);
        __nv_bfloat16 h8 = __float2bfloat16_rn(x8), h9 = __float2bfloat16_rn(x9);
        uint4 o;
        o.x = pack_bf16(x0, x1);  // hi pair (rounding applied by pack)
        o.y = pack_bf16(x8, x9);
        o.z = pack_bf16(x0 - __bfloat162float(h0), x1 - __bfloat162float(h1));
        o.w = pack_bf16(x8 - __bfloat162float(h8), x9 - __bfloat162float(h9));
        *(uint4*)&out[((size_t)((size_t)kt * NT + nt) * 1024 + slot) * 4] = o;
    }
}

// ---------------- bf16x2 (3-term) tensor-core GEMM ----------------
// C[M,N] = (Res?) + A[M,K] @ Bprep, 128x128x32 tiles, 8 warps (2x4),
// warp tile 64x32 of m16n8k16. A split hi/lo at STS; B cp.async from prepped global.
__global__ __launch_bounds__(256) void gemm_bf16x2_kernel(
    const float* __restrict__ A, const uint32_t* __restrict__ Bp,
    const float* __restrict__ Res, float* __restrict__ C,
    int M, int N, int K) {
    // Asm: [ik(2)][im(8)][hl(2)][lane(32)][reg(4)] ; Bsm: [slot(1024)][4]
    __shared__ uint32_t Asm[2][4096];
    __shared__ uint32_t Bsm[2][4096];

    int tid = threadIdx.x, lane = tid & 31, warp = tid >> 5;
    int wm = warp >> 2, wn = warp & 3;
    int bm = blockIdx.y * 128, bnx = blockIdx.x;
    int NT = N >> 7, KT = K >> 5;

    float acc[4][4][4];
#pragma unroll
    for (int im = 0; im < 4; im++)
#pragma unroll
        for (int in = 0; in < 4; in++)
#pragma unroll
            for (int r = 0; r < 4; r++) acc[im][in][r] = 0.f;

    float4 pa[4];

#define LDGA(kt)                                                                     \
    {                                                                                \
        _Pragma("unroll")                                                            \
        for (int i = 0; i < 4; i++) {                                                \
            int f = tid + i * 256;                                                   \
            pa[i] = *(const float4*)(A + (size_t)(bm + (f >> 3)) * K + (kt) * 32 + ((f & 7) << 2)); \
        }                                                                            \
    }

#define CPB(kt, st)                                                                  \
    {                                                                                \
        _Pragma("unroll")                                                            \
        for (int i = 0; i < 4; i++) {                                                \
            int slot = tid + i * 256;                                                \
            cp_async16(&Bsm[st][slot * 4],                                           \
                       Bp + ((size_t)((size_t)(kt) * NT + bnx) * 1024 + slot) * 4);  \
        }                                                                            \
    }

#define STSA(st)                                                                     \
    {                                                                                \
        _Pragma("unroll")                                                            \
        for (int i = 0; i < 4; i++) {                                                \
            int f = tid + i * 256;                                                   \
            int row = f >> 3, k0 = (f & 7) << 2;                                     \
            int ik = k0 >> 4, h = (k0 >> 3) & 1, c0 = (k0 & 7) >> 1;                 \
            int im = row >> 4, reg = ((row >> 3) & 1) + (h << 1);                    \
            int lane0 = ((row & 7) << 2) + c0;                                       \
            float4 v = pa[i];                                                        \
            __nv_bfloat16 h0 = __float2bfloat16_rn(v.x), h1 = __float2bfloat16_rn(v.y); \
            __nv_bfloat16 h2 = __float2bfloat16_rn(v.z), h3 = __float2bfloat16_rn(v.w); \
            int baseHi = ((ik * 8 + im) * 2 + 0) * 32;                               \
            int baseLo = ((ik * 8 + im) * 2 + 1) * 32;                               \
            Asm[st][(baseHi + lane0) * 4 + reg]     = pack_bf16(v.x, v.y);           \
            Asm[st][(baseHi + lane0 + 1) * 4 + reg] = pack_bf16(v.z, v.w);           \
            Asm[st][(baseLo + lane0) * 4 + reg]     =                                \
                pack_bf16(v.x - __bfloat162float(h0), v.y - __bfloat162float(h1));   \
            Asm[st][(baseLo + lane0 + 1) * 4 + reg] =                                \
                pack_bf16(v.z - __bfloat162float(h2), v.w - __bfloat162float(h3));   \
        }                                                                            \
    }

#define COMPUTE(st)                                                                  \
    {                                                                                \
        _Pragma("unroll")                                                            \
        for (int ik = 0; ik < 2; ik++) {                                             \
            uint32_t ah[4][4], al[4][4], bh[4][2], bl[4][2];                         \
            _Pragma("unroll")                                                        \
            for (int im = 0; im < 4; im++) {                                         \
                *(uint4*)ah[im] = *(const uint4*)&Asm[st][(((ik * 8 + wm * 4 + im) * 2 + 0) * 32 + lane) * 4]; \
                *(uint4*)al[im] = *(const uint4*)&Asm[st][(((ik * 8 + wm * 4 + im) * 2 + 1) * 32 + lane) * 4]; \
            }                                                                        \
            _Pragma("unroll")                                                        \
            for (int in = 0; in < 4; in++) {                                         \
                uint4 qv = *(const uint4*)&Bsm[st][((ik * 16 + wn * 4 + in) * 32 + lane) * 4]; \
                bh[in][0] = qv.x; bh[in][1] = qv.y;                                  \
                bl[in][0] = qv.z; bl[in][1] = qv.w;                                  \
            }                                                                        \
            _Pragma("unroll")                                                        \
            for (int im = 0; im < 4; im++)                                           \
                _Pragma("unroll")                                                    \
                for (int in = 0; in < 4; in++) {                                     \
                    mma_bf16(acc[im][in], ah[im], bl[in]);                           \
                    mma_bf16(acc[im][in], al[im], bh[in]);                           \
                    mma_bf16(acc[im][in], ah[im], bh[in]);                           \
                }                                                                    \
        }                                                                            \
    }

    LDGA(0);
    CPB(0, 0); CP_COMMIT();
    STSA(0);
    CP_WAIT0();
    __syncthreads();

    for (int kt = 0; kt < KT; kt++) {
        int st = kt & 1;
        if (kt + 1 < KT) { LDGA(kt + 1); CPB(kt + 1, st ^ 1); CP_COMMIT(); }
        COMPUTE(st);
        if (kt + 1 < KT) { STSA(st ^ 1); CP_WAIT0(); }
        __syncthreads();
    }

    // ---- epilogue ----
    int gid = lane >> 2, tig = lane & 3;
#pragma unroll
    for (int im = 0; im < 4; im++) {
#pragma unroll
        for (int in = 0; in < 4; in++) {
            int row0 = bm + wm * 64 + im * 16 + gid;
            int col = bnx * 128 + wn * 32 + in * 8 + tig * 2;
            float2 v0 = make_float2(acc[im][in][0], acc[im][in][1]);
            float2 v1 = make_float2(acc[im][in][2], acc[im][in][3]);
            if (Res) {
                float2 r0 = *(const float2*)(Res + (size_t)row0 * N + col);
                float2 r1 = *(const float2*)(Res + (size_t)(row0 + 8) * N + col);
                v0.x += r0.x; v0.y += r0.y;
                v1.x += r1.x; v1.y += r1.y;
            }
            *(float2*)(C + (size_t)row0 * N + col) = v0;
            *(float2*)(C + (size_t)(row0 + 8) * N + col) = v1;
        }
    }
#undef LDGA
#undef CPB
#undef STSA
#undef COMPUTE
}

// ---------------- embedding + audio scatter ----------------
__global__ void embed_scatter_kernel(const int* __restrict__ ids,
                                     const float* __restrict__ emb,
                                     const float* __restrict__ audio,
                                     const int* __restrict__ aoff,
                                     float* __restrict__ h) {
    int s = blockIdx.x;
    int off = aoff[0];
    const float* src;
    if (s >= off && s < off + 256) src = audio + (size_t)(s - off) * HDIM;
    else                           src = emb + (size_t)ids[s] * HDIM;
    float* dst = h + (size_t)s * HDIM;
    int i = threadIdx.x * 4;
    *(float4*)&dst[i] = *(const float4*)&src[i];
}

// ---------------- RMSNorm over H=1024 ----------------
__global__ void rmsnorm_kernel(const float* __restrict__ x,
                               const float* __restrict__ w,
                               float* __restrict__ out) {
    int s = blockIdx.x;
    const float* xr = x + (size_t)s * HDIM;
    float ss = 0.f;
#pragma unroll
    for (int i = 0; i < 4; i++) { float v = xr[threadIdx.x + i * 256]; ss += v * v; }
    __shared__ float red[8];
#pragma unroll
    for (int o = 16; o; o >>= 1) ss += __shfl_xor_sync(0xffffffffu, ss, o);
    if ((threadIdx.x & 31) == 0) red[threadIdx.x >> 5] = ss;
    __syncthreads();
    if (threadIdx.x < 32) {
        float v = (threadIdx.x < 8) ? red[threadIdx.x] : 0.f;
#pragma unroll
        for (int o = 4; o; o >>= 1) v += __shfl_xor_sync(0xffffffffu, v, o);
        if (threadIdx.x == 0) red[0] = v;
    }
    __syncthreads();
    float r = rsqrtf(red[0] * (1.f / HDIM) + 1e-6f);
    float* orow = out + (size_t)s * HDIM;
#pragma unroll
    for (int i = 0; i < 4; i++) { int id = threadIdx.x + i * 256; orow[id] = xr[id] * r * w[id]; }
}

// ---------------- per-head RMSNorm (HD=64) + RoPE (strided in/out) ----------------
__global__ void rms_rope_kernel(const float* __restrict__ in, int stride,
                                const float* __restrict__ w,
                                const int* __restrict__ pos_ids,
                                float* __restrict__ out_nat,
                                float* __restrict__ out_T,
                                float* __restrict__ present,
                                int nh) {
    int s = blockIdx.x;
    int warp = threadIdx.x >> 5, lane = threadIdx.x & 31;
    int h = blockIdx.y * 4 + warp;
    if (h >= nh) return;
    const float* x = in + (size_t)s * stride + h * HD;
    float x0 = x[lane], x1 = x[lane + 32];
    float ss = x0 * x0 + x1 * x1;
#pragma unroll
    for (int o = 16; o; o >>= 1) ss += __shfl_xor_sync(0xffffffffu, ss, o);
    float r = rsqrtf(ss * (1.f / HD) + 1e-6f);
    x0 = x0 * r * w[lane];
    x1 = x1 * r * w[lane + 32];
    float pos = (float)pos_ids[s];
    float invf = expf(-((float)lane * (1.f / 32.f)) * 9.210340371976184f);
    float ang = pos * invf;
    float c, sn;
    sincosf(ang, &sn, &c);
    float o0 = x0 * c - x1 * sn;
    float o1 = x1 * c + x0 * sn;
    if (out_nat) {
        float* op = out_nat + (size_t)s * stride + h * HD;
        op[lane] = o0; op[lane + 32] = o1;
    }
    if (out_T) {
        out_T[(size_t)(h * HD + lane) * SEQ + s] = o0;
        out_T[(size_t)(h * HD + lane + 32) * SEQ + s] = o1;
    }
    if (present) {
        float* pp = present + ((size_t)h * SEQ + s) * HD;
        pp[lane] = o0; pp[lane + 32] = o1;
    }
}

// ---------------- copy V (from fused qkv) into present_values [NKV,S,HD] ----------------
__global__ void copy_v_kernel(const float* __restrict__ qkv, float* __restrict__ pv) {
    int s = blockIdx.x;
    int t = threadIdx.x;
    int kv = t >> 6, d = t & 63;
    pv[((size_t)kv * SEQ + s) * HD + d] = qkv[(size_t)s * QKVN + 1280 + t];
}

// ---------------- flash attention: 64q x 64k tiles, online softmax ----------------
// q strided QKVN; v = qkv + 1280, strided QKVN.
__global__ __launch_bounds__(256) void attn_kernel(const float* __restrict__ q,
                                                   const float* __restrict__ kT,
                                                   const float* __restrict__ v,
                                                   float* __restrict__ o) {
    extern __shared__ float sm[];
    float* Qs  = sm;
    float* Kst = sm + 4096;
    float* Vs  = sm + 8192;
    float* Ps  = sm + 12288;
    int qt = blockIdx.x, h = blockIdx.y, kvh = h >> 2;
    int tid = threadIdx.x;
    int tr = tid >> 4, tc = tid & 15;

#pragma unroll
    for (int it = 0; it < 4; it++) {
        int idx = tid + it * 256;
        int rr = idx >> 4, dv = (idx & 15) << 2;
        *(float4*)&Qs[rr * 64 + dv] =
            *(const float4*)&q[(size_t)(qt * 64 + rr) * QKVN + h * HD + dv];
    }

    float m[4], l[4], acc[4][4];
#pragma unroll
    for (int i = 0; i < 4; i++) {
        m[i] = -1e30f; l[i] = 0.f;
#pragma unroll
        for (int j = 0; j < 4; j++) acc[i][j] = 0.f;
    }

    for (int kt = 0; kt <= qt; kt++) {
        __syncthreads();
#pragma unroll
        for (int it = 0; it < 4; it++) {
            int idx = tid + it * 256;
            int a = idx >> 4, bv = (idx & 15) << 2;
            *(float4*)&Kst[a * 64 + bv] =
                *(const float4*)&kT[(size_t)(kvh * HD + a) * SEQ + kt * 64 + bv];
            *(float4*)&Vs[a * 64 + bv] =
                *(const float4*)&v[(size_t)(kt * 64 + a) * QKVN + kvh * HD + bv];
        }
        __syncthreads();

        float sc[4][4];
#pragma unroll
        for (int i = 0; i < 4; i++)
#pragma unroll
            for (int j = 0; j < 4; j++) sc[i][j] = 0.f;

#pragma unroll 8
        for (int d = 0; d < 64; d++) {
            float4 b = *(float4*)&Kst[d * 64 + tc * 4];
            float a0 = Qs[(tr * 4 + 0) * 64 + d];
            float a1 = Qs[(tr * 4 + 1) * 64 + d];
            float a2 = Qs[(tr * 4 + 2) * 64 + d];
            float a3 = Qs[(tr * 4 + 3) * 64 + d];
            sc[0][0] += a0 * b.x; sc[0][1] += a0 * b.y; sc[0][2] += a0 * b.z; sc[0][3] += a0 * b.w;
            sc[1][0] += a1 * b.x; sc[1][1] += a1 * b.y; sc[1][2] += a1 * b.z; sc[1][3] += a1 * b.w;
            sc[2][0] += a2 * b.x; sc[2][1] += a2 * b.y; sc[2][2] += a2 * b.z; sc[2][3] += a2 * b.w;
            sc[3][0] += a3 * b.x; sc[3][1] += a3 * b.y; sc[3][2] += a3 * b.z; sc[3][3] += a3 * b.w;
        }

        bool diag = (kt == qt);
#pragma unroll
        for (int i = 0; i < 4; i++) {
            int qrow = qt * 64 + tr * 4 + i;
            float tm_ = -1e30f;
#pragma unroll
            for (int j = 0; j < 4; j++) {
                float val = sc[i][j] * 0.125f;
                if (diag && (kt * 64 + tc * 4 + j) > qrow) val = -1e30f;
                sc[i][j] = val;
                tm_ = fmaxf(tm_, val);
            }
            tm_ = fmaxf(tm_, __shfl_xor_sync(0xffffffffu, tm_, 1));
            tm_ = fmaxf(tm_, __shfl_xor_sync(0xffffffffu, tm_, 2));
            tm_ = fmaxf(tm_, __shfl_xor_sync(0xffffffffu, tm_, 4));
            tm_ = fmaxf(tm_, __shfl_xor_sync(0xffffffffu, tm_, 8));
            float mn = fmaxf(m[i], tm_);
            float scal = expf(m[i] - mn);
            float ps = 0.f;
#pragma unroll
            for (int j = 0; j < 4; j++) {
                float p = expf(sc[i][j] - mn);
                sc[i][j] = p;
                ps += p;
            }
            ps += __shfl_xor_sync(0xffffffffu, ps, 1);
            ps += __shfl_xor_sync(0xffffffffu, ps, 2);
            ps += __shfl_xor_sync(0xffffffffu, ps, 4);
            ps += __shfl_xor_sync(0xffffffffu, ps, 8);
            l[i] = l[i] * scal + ps;
            m[i] = mn;
#pragma unroll
            for (int j = 0; j < 4; j++) {
                acc[i][j] *= scal;
                Ps[(tr * 4 + i) * 64 + tc * 4 + j] = sc[i][j];
            }
        }
        __syncwarp();

#pragma unroll 8
        for (int j = 0; j < 64; j++) {
            float4 b = *(float4*)&Vs[j * 64 + tc * 4];
            float p0 = Ps[(tr * 4 + 0) * 64 + j];
            float p1 = Ps[(tr * 4 + 1) * 64 + j];
            float p2 = Ps[(tr * 4 + 2) * 64 + j];
            float p3 = Ps[(tr * 4 + 3) * 64 + j];
            acc[0][0] += p0 * b.x; acc[0][1] += p0 * b.y; acc[0][2] += p0 * b.z; acc[0][3] += p0 * b.w;
            acc[1][0] += p1 * b.x; acc[1][1] += p1 * b.y; acc[1][2] += p1 * b.z; acc[1][3] += p1 * b.w;
            acc[2][0] += p2 * b.x; acc[2][1] += p2 * b.y; acc[2][2] += p2 * b.z; acc[2][3] += p2 * b.w;
            acc[3][0] += p3 * b.x; acc[3][1] += p3 * b.y; acc[3][2] += p3 * b.z; acc[3][3] += p3 * b.w;
        }
    }

#pragma unroll
    for (int i = 0; i < 4; i++) {
        float inv = 1.f / l[i];
        int row = qt * 64 + tr * 4 + i;
        float4 ov;
        ov.x = acc[i][0] * inv; ov.y = acc[i][1] * inv;
        ov.z = acc[i][2] * inv; ov.w = acc[i][3] * inv;
        *(float4*)&o[(size_t)row * (NH * HD) + h * HD + tc * 4] = ov;
    }
}

// ---------------- silu(g) * u from fused gu ----------------
__global__ void silu_mul_kernel(const float* __restrict__ gu, float* __restrict__ out, int n) {
    int i = blockIdx.x * 256 + threadIdx.x;
    if (i < n) {
        int s = i >> 12, c = i & 4095;
        float x = gu[(size_t)s * GUN + c];
        float u = gu[(size_t)s * GUN + IDIM + c];
        out[i] = x / (1.f + expf(-x)) * u;
    }
}

// ---------------- host launch ----------------
extern "C" void kernel_launch(void* const* d_in, const int* in_sizes, int n_in,
                              void* d_out, int out_size) {
    (void)in_sizes; (void)n_in; (void)out_size;

    static bool init = false;
    static float *p_h, *p_norm, *p_qkv, *p_kT, *p_att, *p_gu, *p_act;
    static uint32_t *p_wqkv, *p_wo, *p_wgu, *p_wdown, *p_wlm;
    if (!init) {
        cudaGetSymbolAddress((void**)&p_h, g_h);
        cudaGetSymbolAddress((void**)&p_norm, g_norm);
        cudaGetSymbolAddress((void**)&p_qkv, g_qkv);
        cudaGetSymbolAddress((void**)&p_kT, g_kT);
        cudaGetSymbolAddress((void**)&p_att, g_att);
        cudaGetSymbolAddress((void**)&p_gu, g_gu);
        cudaGetSymbolAddress((void**)&p_act, g_act);
        cudaGetSymbolAddress((void**)&p_wqkv, wp_qkv);
        cudaGetSymbolAddress((void**)&p_wo, wp_o);
        cudaGetSymbolAddress((void**)&p_wgu, wp_gu);
        cudaGetSymbolAddress((void**)&p_wdown, wp_down);
        cudaGetSymbolAddress((void**)&p_wlm, wp_lm);
        cudaFuncSetAttribute(attn_kernel, cudaFuncAttributeMaxDynamicSharedMemorySize, 65536);
        init = true;
    }

    const int*   ids    = (const int*)d_in[0];
    const int*   pos    = (const int*)d_in[1];
    const float* audio  = (const float*)d_in[2];
    const int*   aoff   = (const int*)d_in[3];
    const float* embw   = (const float*)d_in[4];
    const float* q_w    = (const float*)d_in[5];
    const float* k_w    = (const float*)d_in[6];
    const float* v_w    = (const float*)d_in[7];
    const float* o_w    = (const float*)d_in[8];
    const float* qn_w   = (const float*)d_in[9];
    const float* kn_w   = (const float*)d_in[10];
    const float* ln1_w  = (const float*)d_in[11];
    const float* ln2_w  = (const float*)d_in[12];
    const float* gate_w = (const float*)d_in[13];
    const float* up_w   = (const float*)d_in[14];
    const float* down_w = (const float*)d_in[15];
    const float* norm_w = (const float*)d_in[16];
    const float* lm_w   = (const float*)d_in[17];

    float* out    = (float*)d_out;
    float* logits = out;
    float* pk     = out + (size_t)SEQ * VOCAB;
    float* pv     = pk + (size_t)NLAYER * NKV * SEQ * HD;

    const int BIG = 1 << 30;

    // ---- weight prep (deterministic; every call) ----
    for (int l = 0; l < NLAYER; l++) {
        prep_w_kernel<<<dim3(QKVN / 128, HDIM / 32), 256>>>(
            q_w + (size_t)l * HDIM * (NH * HD), NH * HD,
            k_w + (size_t)l * HDIM * (NKV * HD), NKV * HD,
            v_w + (size_t)l * HDIM * (NKV * HD), NKV * HD,
            NH * HD, NH * HD + NKV * HD,
            p_wqkv + (size_t)l * HDIM * QKVN);
        prep_w_kernel<<<dim3(HDIM / 128, HDIM / 32), 256>>>(
            o_w + (size_t)l * HDIM * HDIM, HDIM, o_w, HDIM, o_w, HDIM, BIG, BIG,
            p_wo + (size_t)l * HDIM * HDIM);
        prep_w_kernel<<<dim3(GUN / 128, HDIM / 32), 256>>>(
            gate_w + (size_t)l * HDIM * IDIM, IDIM,
            up_w + (size_t)l * HDIM * IDIM, IDIM,
            up_w, IDIM, IDIM, BIG,
            p_wgu + (size_t)l * HDIM * GUN);
        prep_w_kernel<<<dim3(HDIM / 128, IDIM / 32), 256>>>(
            down_w + (size_t)l * IDIM * HDIM, HDIM, down_w, HDIM, down_w, HDIM, BIG, BIG,
            p_wdown + (size_t)l * IDIM * HDIM);
    }
    prep_w_kernel<<<dim3(VOCAB / 128, HDIM / 32), 256>>>(
        lm_w, VOCAB, lm_w, VOCAB, lm_w, VOCAB, BIG, BIG, p_wlm);

    embed_scatter_kernel<<<SEQ, 256>>>(ids, embw, audio, aoff, p_h);

    for (int l = 0; l < NLAYER; l++) {
        rmsnorm_kernel<<<SEQ, 256>>>(p_h, ln1_w + (size_t)l * HDIM, p_norm);

        gemm_bf16x2_kernel<<<dim3(QKVN / 128, SEQ / 128), 256>>>(
            p_norm, p_wqkv + (size_t)l * HDIM * QKVN, nullptr, p_qkv, SEQ, QKVN, HDIM);

        rms_rope_kernel<<<dim3(SEQ, 4), 128>>>(p_qkv, QKVN, qn_w + (size_t)l * HD, pos,
                                               p_qkv, nullptr, nullptr, NH);
        rms_rope_kernel<<<dim3(SEQ, 1), 128>>>(p_qkv + NH * HD, QKVN, kn_w + (size_t)l * HD, pos,
                                               nullptr, p_kT,
                                               pk + (size_t)l * NKV * SEQ * HD, NKV);
        copy_v_kernel<<<SEQ, 256>>>(p_qkv, pv + (size_t)l * NKV * SEQ * HD);

        attn_kernel<<<dim3(SEQ / 64, NH), 256, 65536>>>(p_qkv, p_kT, p_qkv + 1280, p_att);

        gemm_bf16x2_kernel<<<dim3(HDIM / 128, SEQ / 128), 256>>>(
            p_att, p_wo + (size_t)l * HDIM * HDIM, p_h, p_h, SEQ, HDIM, HDIM);

        rmsnorm_kernel<<<SEQ, 256>>>(p_h, ln2_w + (size_t)l * HDIM, p_norm);

        gemm_bf16x2_kernel<<<dim3(GUN / 128, SEQ / 128), 256>>>(
            p_norm, p_wgu + (size_t)l * HDIM * GUN, nullptr, p_gu, SEQ, GUN, HDIM);

        silu_mul_kernel<<<(SEQ * IDIM) / 256, 256>>>(p_gu, p_act, SEQ * IDIM);

        gemm_bf16x2_kernel<<<dim3(HDIM / 128, SEQ / 128), 256>>>(
            p_act, p_wdown + (size_t)l * IDIM * HDIM, p_h, p_h, SEQ, HDIM, IDIM);
    }

    rmsnorm_kernel<<<SEQ, 256>>>(p_h, norm_w, p_norm);
    gemm_bf16x2_kernel<<<dim3(VOCAB / 128, SEQ / 128), 256>>>(
        p_norm, p_wlm, nullptr, logits, SEQ, VOCAB, HDIM);
}